// round 9
// baseline (speedup 1.0000x reference)
#include <cuda_runtime.h>
#include <cfloat>

#define Bn 512
#define Tn 512
#define Kn 64
#define PD 4  // potentials prefetch ring depth (registers)

__device__ int g_seq[Bn];

// Monotone float <-> uint order-preserving map (finite floats).
__device__ __forceinline__ unsigned fmap(float f) {
    int i = __float_as_int(f);
    return (unsigned)(i >= 0 ? (i ^ 0x80000000) : ~i);
}
__device__ __forceinline__ float funmap(unsigned u) {
    int i = (u & 0x80000000u) ? (int)(u ^ 0x80000000u) : ~(int)u;
    return __int_as_float(i);
}

// ---------------------------------------------------------------------------
// Kernel 1: seq_lens[b] = int( mean_k( sum_t (x[b,t,k] != 0) ) )  (exact)
// ---------------------------------------------------------------------------
__global__ __launch_bounds__(256) void seqlen_kernel(const float* __restrict__ x) {
    __shared__ int red[256];
    const int b = blockIdx.x;
    const float4* xb = (const float4*)(x + (size_t)b * Tn * Kn);
    int c = 0;
    for (int i = threadIdx.x; i < (Tn * Kn) / 4; i += 256) {
        float4 v = xb[i];
        c += (v.x != 0.0f) + (v.y != 0.0f) + (v.z != 0.0f) + (v.w != 0.0f);
    }
    red[threadIdx.x] = c;
    __syncthreads();
    for (int s = 128; s > 0; s >>= 1) {
        if (threadIdx.x < s) red[threadIdx.x] += red[threadIdx.x + s];
        __syncthreads();
    }
    if (threadIdx.x == 0) g_seq[b] = red[0] >> 6;  // floor(total / 64)
}

// ---------------------------------------------------------------------------
// Exact full 64-candidate scan (general path). First max wins.
// ---------------------------------------------------------------------------
__device__ __noinline__ void full_scan64(
    float a_lo, float a_hi, const float2* trans2, int l,
    float& best0, float& best1, int& bi0, int& bi1)
{
    float b0 = -FLT_MAX, b1 = -FLT_MAX;
    int x0 = 0, x1 = 0;
#pragma unroll 4
    for (int i = 0; i < Kn; i++) {
        const float asel = (i < 32) ? a_lo : a_hi;
        const float av = __shfl_sync(0xffffffffu, asel, i & 31);
        const float2 tv = trans2[i * 32 + l];
        const float s0 = av + tv.x, s1 = av + tv.y;
        const bool g0 = s0 > b0; b0 = g0 ? s0 : b0; x0 = g0 ? i : x0;
        const bool g1 = s1 > b1; b1 = g1 ? s1 : b1; x1 = g1 ? i : x1;
    }
    best0 = b0; best1 = b1; bi0 = x0; bi1 = x1;
}

// Candidate fetch: alpha[i] via shuffle (uniform lane), trans column pair.
#define FETCH(i_, s0_, s1_)                                                 \
    {                                                                       \
        const float asel_ = ((i_) < 32) ? a_lo : a_hi;                      \
        const float av_ = __shfl_sync(0xffffffffu, asel_, (i_) & 31);       \
        const float2 tv_ = trans2[(i_) * 32 + l];                           \
        s0_ = av_ + tv_.x;                                                  \
        s1_ = av_ + tv_.y;                                                  \
    }

// One DP step (fast path, t < sl guaranteed). S_ = t&3, S1_ = (t+1)&3.
// thr_ for the end-of-step ballot is the STALE-SAFE bound:
//   thr_t = W_{t-1} + maxP_t + minT - rT - pad  (uW, uP redux'd one step ago,
//   so their latency is fully hidden; pad absorbs all float rounding and
//   only ever ADDS candidates -> exact).
#define STEP_F(T_, S_, S1_)                                                  \
    {                                                                        \
        const int t_ = (T_);                                                 \
        const float p_lo = plo[S_];                                          \
        const float p_hi = phi[S_];                                          \
        {                                                                    \
            const int tl_ = (t_ + PD <= Tn - 1) ? (t_ + PD) : (Tn - 1);      \
            plo[S_] = pb[tl_ * Kn + l];                                      \
            phi[S_] = pb[tl_ * Kn + 32 + l];                                 \
        }                                                                    \
        const float thr_ = funmap(uW) + (funmap(uP) + fconst);               \
        const unsigned long long M =                                         \
            ((unsigned long long)m_hi << 32) | (unsigned long long)m_lo;     \
        /* 8 lowest candidates, ascending, duplicate-padded when C<8 */      \
        unsigned long long m_ = M;                                           \
        const int i0 = __ffsll((long long)m_) - 1;            m_ &= m_ - 1;  \
        const int i1 = m_ ? __ffsll((long long)m_) - 1 : i0;  m_ &= m_ - 1;  \
        const int i2 = m_ ? __ffsll((long long)m_) - 1 : i1;  m_ &= m_ - 1;  \
        const int i3 = m_ ? __ffsll((long long)m_) - 1 : i2;  m_ &= m_ - 1;  \
        const int i4 = m_ ? __ffsll((long long)m_) - 1 : i3;  m_ &= m_ - 1;  \
        const int i5 = m_ ? __ffsll((long long)m_) - 1 : i4;  m_ &= m_ - 1;  \
        const int i6 = m_ ? __ffsll((long long)m_) - 1 : i5;  m_ &= m_ - 1;  \
        const int i7 = m_ ? __ffsll((long long)m_) - 1 : i6;                 \
        unsigned long long Mrest = m_ & (m_ - 1);                            \
        float sa0, sb0, sa1, sb1, sa2, sb2, sa3, sb3;                        \
        float sa4, sb4, sa5, sb5, sa6, sb6, sa7, sb7;                        \
        FETCH(i0, sa0, sb0); FETCH(i1, sa1, sb1);                            \
        FETCH(i2, sa2, sb2); FETCH(i3, sa3, sb3);                            \
        FETCH(i4, sa4, sb4); FETCH(i5, sa5, sb5);                            \
        FETCH(i6, sa6, sb6); FETCH(i7, sa7, sb7);                            \
        /* max tree (FMNMX); best is bitwise one of the candidates */        \
        float best0, best1;                                                  \
        {                                                                    \
            const float q0 = fmaxf(sa0, sa1), q1 = fmaxf(sa2, sa3);          \
            const float q2 = fmaxf(sa4, sa5), q3 = fmaxf(sa6, sa7);          \
            best0 = fmaxf(fmaxf(q0, q1), fmaxf(q2, q3));                     \
            const float r0 = fmaxf(sb0, sb1), r1 = fmaxf(sb2, sb3);          \
            const float r2 = fmaxf(sb4, sb5), r3 = fmaxf(sb6, sb7);          \
            best1 = fmaxf(fmaxf(r0, r1), fmaxf(r2, r3));                     \
        }                                                                    \
        /* ascending first-index recovery: i0 applied last -> smallest      \
           index among value-ties wins == jnp.argmax first-max (exact) */    \
        int bi0 = i7, bi1 = i7;                                              \
        bi0 = (sa6 == best0) ? i6 : bi0;  bi1 = (sb6 == best1) ? i6 : bi1;   \
        bi0 = (sa5 == best0) ? i5 : bi0;  bi1 = (sb5 == best1) ? i5 : bi1;   \
        bi0 = (sa4 == best0) ? i4 : bi0;  bi1 = (sb4 == best1) ? i4 : bi1;   \
        bi0 = (sa3 == best0) ? i3 : bi0;  bi1 = (sb3 == best1) ? i3 : bi1;   \
        bi0 = (sa2 == best0) ? i2 : bi0;  bi1 = (sb2 == best1) ? i2 : bi1;   \
        bi0 = (sa1 == best0) ? i1 : bi0;  bi1 = (sb1 == best1) ? i1 : bi1;   \
        bi0 = (sa0 == best0) ? i0 : bi0;  bi1 = (sb0 == best1) ? i0 : bi1;   \
        if (Mrest) { /* rare: C > 8; continue ascending, strict > (exact) */ \
            do {                                                             \
                const int i_ = __ffsll((long long)Mrest) - 1;                \
                Mrest &= Mrest - 1;                                          \
                float s0_, s1_;                                              \
                FETCH(i_, s0_, s1_);                                         \
                { const bool g = s0_ > best0;                                \
                  best0 = g ? s0_ : best0;  bi0 = g ? i_ : bi0; }            \
                { const bool g = s1_ > best1;                                \
                  best1 = g ? s1_ : best1;  bi1 = g ? i_ : bi1; }            \
            } while (Mrest);                                                 \
        }                                                                    \
        a_lo = p_lo + best0;                                                 \
        a_hi = p_hi + best1;                                                 \
        bp[(t_ - 1) * Kn + l] = (unsigned char)bi0;                          \
        bp[(t_ - 1) * Kn + 32 + l] = (unsigned char)bi1;                     \
        /* off-chain collectives for NEXT step's threshold */                \
        {                                                                    \
            const unsigned am_ = fmap(a_lo), ah_ = fmap(a_hi);               \
            uW = __reduce_max_sync(0xffffffffu, am_ > ah_ ? am_ : ah_);      \
            const unsigned pl_ = fmap(plo[S1_]), ph_ = fmap(phi[S1_]);       \
            uP = __reduce_max_sync(0xffffffffu, pl_ > ph_ ? pl_ : ph_);      \
        }                                                                    \
        m_lo = __ballot_sync(0xffffffffu, a_lo >= thr_);                     \
        m_hi = __ballot_sync(0xffffffffu, a_hi >= thr_);                     \
    }

// ---------------------------------------------------------------------------
// Kernel 2: single-warp Viterbi with stale-safe pruned step.
// ---------------------------------------------------------------------------
__global__ __launch_bounds__(32) void viterbi_kernel(
    const float* __restrict__ pots,   // [B, T, K]
    const float* __restrict__ trans,  // [K, K]
    float* __restrict__ out)          // [B, T] float32
{
    extern __shared__ float2 trans2[];            // [64][32]: (T[i][l], T[i][l+32])
    __shared__ unsigned char bp[(Tn - 1) * Kn];   // 32704 B
    __shared__ unsigned char tags[Tn];
    __shared__ float alpha_f[Kn];

    const int b = blockIdx.x;
    const int l = threadIdx.x;  // lane; owns to-tags l and l+32

    // ---- Prologue: stage transitions (float2-packed) + padded range ----
    const float4* tr4 = (const float4*)trans;
    float tmin = FLT_MAX, tmax = -FLT_MAX;
#pragma unroll
    for (int q = 0; q < 32; q++) {
        const int idx = q * 32 + l;
        const float4 v = tr4[idx];
        tmin = fminf(tmin, fminf(fminf(v.x, v.y), fminf(v.z, v.w)));
        tmax = fmaxf(tmax, fmaxf(fmaxf(v.x, v.y), fmaxf(v.z, v.w)));
        const int base = idx * 4;
        const int i = base >> 6;
        const int c = base & 63;
        if (c < 32) {
            trans2[i * 32 + c + 0].x = v.x;
            trans2[i * 32 + c + 1].x = v.y;
            trans2[i * 32 + c + 2].x = v.z;
            trans2[i * 32 + c + 3].x = v.w;
        } else {
            const int cc = c - 32;
            trans2[i * 32 + cc + 0].y = v.x;
            trans2[i * 32 + cc + 1].y = v.y;
            trans2[i * 32 + cc + 2].y = v.z;
            trans2[i * 32 + cc + 3].y = v.w;
        }
    }
    const unsigned rmn = __reduce_min_sync(0xffffffffu, fmap(tmin));
    const unsigned rmx = __reduce_max_sync(0xffffffffu, fmap(tmax));
    const float minT = funmap(rmn);
    const float r = funmap(rmx) - minT;
    const float rTp = r + fabsf(r) * 1e-5f + 0.02f;  // pad only ADDS candidates
    const float fconst = minT - rTp;                 // for stale threshold
    __syncwarp();

    const float* pb = pots + (size_t)b * Tn * Kn;
    int sl = g_seq[b];
    if (sl > Tn) sl = Tn;

    float a_lo = pb[l];
    float a_hi = pb[32 + l];

    if (sl >= Tn) {
        // ---------------- FAST PATH: every step active ----------------------
        // Prefetch ring, depth PD=4 (slot = t & 3, compile-time in each STEP).
        float plo[PD], phi[PD];
#pragma unroll
        for (int d = 1; d <= PD; d++) {
            plo[d & (PD - 1)] = pb[d * Kn + l];
            phi[d & (PD - 1)] = pb[d * Kn + 32 + l];
        }
        // W_0 (exact) + initial masks (exact threshold) + P-max over p_1.
        unsigned uW, uP;
        unsigned m_lo, m_hi;
        {
            const unsigned am = fmap(a_lo), ah = fmap(a_hi);
            uW = __reduce_max_sync(0xffffffffu, am > ah ? am : ah);
            const float thr0 = funmap(uW) - rTp;
            m_lo = __ballot_sync(0xffffffffu, a_lo >= thr0);
            m_hi = __ballot_sync(0xffffffffu, a_hi >= thr0);
            const unsigned pl0 = fmap(plo[1]), ph0 = fmap(phi[1]);
            uP = __reduce_max_sync(0xffffffffu, pl0 > ph0 ? pl0 : ph0);
        }

        // t = 1..511: 127 blocks of 4 (t=1..508) + 3 remainder.
        int t = 1;
#pragma unroll 1
        for (int tb = 0; tb < 127; tb++) {
            STEP_F(t + 0, 1, 2); STEP_F(t + 1, 2, 3);
            STEP_F(t + 2, 3, 0); STEP_F(t + 3, 0, 1);
            t += 4;
        }
        STEP_F(t + 0, 1, 2); STEP_F(t + 1, 2, 3); STEP_F(t + 2, 3, 0);
    } else {
        // ---------------- GENERAL PATH (rare): exact full scan ---------------
#pragma unroll 1
        for (int t = 1; t < Tn; t++) {
            if (t < sl) {
                float best0, best1; int bi0, bi1;
                full_scan64(a_lo, a_hi, trans2, l, best0, best1, bi0, bi1);
                a_lo = pb[t * Kn + l] + best0;
                a_hi = pb[t * Kn + 32 + l] + best1;
                bp[(t - 1) * Kn + l] = (unsigned char)bi0;
                bp[(t - 1) * Kn + 32 + l] = (unsigned char)bi1;
            } else {
                bp[(t - 1) * Kn + l] = (unsigned char)l;
                bp[(t - 1) * Kn + 32 + l] = (unsigned char)(32 + l);
            }
        }
    }

    // Final alpha -> smem for the backtrace scan
    alpha_f[l] = a_lo;
    alpha_f[32 + l] = a_hi;
    __syncwarp();

    // Backtrace (smem pointer-chase) by lane 0. First max wins.
    if (l == 0) {
        float bv = alpha_f[0];
        int bt = 0;
#pragma unroll 1
        for (int i = 1; i < Kn; i++) {
            const float v = alpha_f[i];
            if (v > bv) { bv = v; bt = i; }
        }
        int tg = bt;
        tags[Tn - 1] = (unsigned char)tg;
#pragma unroll 1
        for (int tt = Tn - 2; tt >= 0; tt--) {
            tg = bp[tt * Kn + tg];
            tags[tt] = (unsigned char)tg;
        }
    }
    __syncwarp();

    // Coalesced float32 output write (16 per lane).
    float* ob = out + (size_t)b * Tn;
#pragma unroll
    for (int tt = l; tt < Tn; tt += 32) ob[tt] = (float)tags[tt];
}

// ---------------------------------------------------------------------------
extern "C" void kernel_launch(void* const* d_in, const int* in_sizes, int n_in,
                              void* d_out, int out_size) {
    const float* inputs = nullptr;
    const float* transitions = nullptr;
    for (int i = 0; i < n_in; i++) {
        if (in_sizes[i] == Kn * Kn) transitions = (const float*)d_in[i];
        else if (in_sizes[i] == Bn * Tn * Kn) inputs = (const float*)d_in[i];
    }
    if (!inputs) inputs = (const float*)d_in[0];
    if (!transitions) transitions = (const float*)d_in[1];

    float* out = (float*)d_out;

    // Static (~33.5 KB) + 16 KB dynamic -> opt in (host config, capture-safe).
    cudaFuncSetAttribute(viterbi_kernel,
                         cudaFuncAttributeMaxDynamicSharedMemorySize,
                         Kn * 32 * (int)sizeof(float2));

    seqlen_kernel<<<Bn, 256>>>(inputs);
    viterbi_kernel<<<Bn, 32, Kn * 32 * sizeof(float2)>>>(inputs, transitions, out);
}

// round 10
// speedup vs baseline: 1.5725x; 1.5725x over previous
#include <cuda_runtime.h>
#include <cfloat>

#define Bn 512
#define Tn 512
#define Kn 64
#define PD 8  // potentials prefetch ring depth (registers)

__device__ int g_seq[Bn];

// Monotone float <-> uint order-preserving map (finite floats).
__device__ __forceinline__ unsigned fmap(float f) {
    const int i = __float_as_int(f);
    return (unsigned)(i ^ ((i >> 31) | 0x80000000));  // SHF + LOP3
}
__device__ __forceinline__ float funmap(unsigned u) {
    const int s = ~((int)u >> 31);  // 0 if u had sign bit, else ~0
    return __int_as_float((int)(u ^ (0x80000000u | (unsigned)s)));
}

// ---------------------------------------------------------------------------
// Kernel 1: seq_lens[b] = int( mean_k( sum_t (x[b,t,k] != 0) ) )  (exact)
// ---------------------------------------------------------------------------
__global__ __launch_bounds__(256) void seqlen_kernel(const float* __restrict__ x) {
    __shared__ int red[256];
    const int b = blockIdx.x;
    const float4* xb = (const float4*)(x + (size_t)b * Tn * Kn);
    int c = 0;
    for (int i = threadIdx.x; i < (Tn * Kn) / 4; i += 256) {
        float4 v = xb[i];
        c += (v.x != 0.0f) + (v.y != 0.0f) + (v.z != 0.0f) + (v.w != 0.0f);
    }
    red[threadIdx.x] = c;
    __syncthreads();
    for (int s = 128; s > 0; s >>= 1) {
        if (threadIdx.x < s) red[threadIdx.x] += red[threadIdx.x + s];
        __syncthreads();
    }
    if (threadIdx.x == 0) g_seq[b] = red[0] >> 6;  // floor(total / 64)
}

// ---------------------------------------------------------------------------
// Exact full 64-candidate scan (general path). First max wins.
// ---------------------------------------------------------------------------
__device__ __noinline__ void full_scan64(
    float a_lo, float a_hi, const float2* trans2, int l,
    float& best0, float& best1, int& bi0, int& bi1)
{
    float b0 = -FLT_MAX, b1 = -FLT_MAX;
    int x0 = 0, x1 = 0;
#pragma unroll 4
    for (int i = 0; i < Kn; i++) {
        const float asel = (i < 32) ? a_lo : a_hi;
        const float av = __shfl_sync(0xffffffffu, asel, i & 31);
        const float2 tv = trans2[i * 32 + l];
        const float s0 = av + tv.x, s1 = av + tv.y;
        const bool g0 = s0 > b0; b0 = g0 ? s0 : b0; x0 = g0 ? i : x0;
        const bool g1 = s1 > b1; b1 = g1 ? s1 : b1; x1 = g1 ? i : x1;
    }
    best0 = b0; best1 = b1; bi0 = x0; bi1 = x1;
}

// Candidate fetch: alpha[i] via shuffle (uniform lane), trans column pair.
#define FETCH(i_, s0_, s1_)                                                 \
    {                                                                       \
        const float asel_ = ((i_) < 32) ? a_lo : a_hi;                      \
        const float av_ = __shfl_sync(0xffffffffu, asel_, (i_) & 31);       \
        const float2 tv_ = trans2[(i_) * 32 + l];                           \
        s0_ = av_ + tv_.x;                                                  \
        s1_ = av_ + tv_.y;                                                  \
    }

// One DP step (fast path, t < sl guaranteed). Ring slot S_ is compile-time.
// EXACT threshold (redux at end of previous step's code, R8 semantics).
// Value path = FMNMX tree (short chain); index recovery via == compares is
// OFF the loop-carried chain (feeds only the bp store).
#define STEP_F(T_, S_)                                                       \
    {                                                                        \
        const int t_ = (T_);                                                 \
        const float p_lo = plo[S_];                                          \
        const float p_hi = phi[S_];                                          \
        {                                                                    \
            const int tl_ = (t_ + PD <= Tn - 1) ? (t_ + PD) : (Tn - 1);      \
            plo[S_] = pb[tl_ * Kn + l];                                      \
            phi[S_] = pb[tl_ * Kn + 32 + l];                                 \
        }                                                                    \
        const unsigned long long M =                                         \
            ((unsigned long long)m_hi << 32) | (unsigned long long)m_lo;     \
        /* 4 lowest candidates, ascending, duplicate-padded when C<4 */      \
        unsigned long long m_ = M;                                           \
        const int i0 = __ffsll((long long)m_) - 1;            m_ &= m_ - 1;  \
        const int i1 = m_ ? __ffsll((long long)m_) - 1 : i0;  m_ &= m_ - 1;  \
        const int i2 = m_ ? __ffsll((long long)m_) - 1 : i1;  m_ &= m_ - 1;  \
        const int i3 = m_ ? __ffsll((long long)m_) - 1 : i2;                 \
        unsigned long long Mrest = m_ & (m_ - 1);                            \
        float sa0, sb0, sa1, sb1, sa2, sb2, sa3, sb3;                        \
        FETCH(i0, sa0, sb0); FETCH(i1, sa1, sb1);                            \
        FETCH(i2, sa2, sb2); FETCH(i3, sa3, sb3);                            \
        /* FMNMX tree: best is bitwise one of the candidates (4+4 cyc) */    \
        float best0 = fmaxf(fmaxf(sa0, sa1), fmaxf(sa2, sa3));               \
        float best1 = fmaxf(fmaxf(sb0, sb1), fmaxf(sb2, sb3));               \
        /* OFF-CHAIN index recovery: descending, i0 last -> smallest index   \
           among value-ties wins == jnp.argmax first-max (exact) */          \
        int bi0 = i3, bi1 = i3;                                              \
        bi0 = (sa2 == best0) ? i2 : bi0;  bi1 = (sb2 == best1) ? i2 : bi1;   \
        bi0 = (sa1 == best0) ? i1 : bi0;  bi1 = (sb1 == best1) ? i1 : bi1;   \
        bi0 = (sa0 == best0) ? i0 : bi0;  bi1 = (sb0 == best1) ? i0 : bi1;   \
        if (Mrest) { /* rare: C > 4; continue ascending, strict > (exact) */ \
            do {                                                             \
                const int i_ = __ffsll((long long)Mrest) - 1;                \
                Mrest &= Mrest - 1;                                          \
                float s0_, s1_;                                              \
                FETCH(i_, s0_, s1_);                                         \
                { const bool g = s0_ > best0;                                \
                  best0 = g ? s0_ : best0;  bi0 = g ? i_ : bi0; }            \
                { const bool g = s1_ > best1;                                \
                  best1 = g ? s1_ : best1;  bi1 = g ? i_ : bi1; }            \
            } while (Mrest);                                                 \
        }                                                                    \
        a_lo = p_lo + best0;                                                 \
        a_hi = p_hi + best1;                                                 \
        /* packed backpointer store: one STS.16 per lane (off-chain) */      \
        bp16[(t_ - 1) * 32 + l] =                                            \
            (unsigned short)((unsigned)bi0 | ((unsigned)bi1 << 8));          \
        /* EXACT threshold for the next step (R8 semantics) */               \
        const unsigned am_ = fmap(a_lo), ah_ = fmap(a_hi);                   \
        const unsigned wm_ =                                                 \
            __reduce_max_sync(0xffffffffu, am_ > ah_ ? am_ : ah_);           \
        const float thr_ = funmap(wm_) - rTp;                                \
        m_lo = __ballot_sync(0xffffffffu, a_lo >= thr_);                     \
        m_hi = __ballot_sync(0xffffffffu, a_hi >= thr_);                     \
    }

// ---------------------------------------------------------------------------
// Kernel 2: single-warp Viterbi, exact-threshold pruned step.
// Candidates = { i : alpha[i] >= max(alpha) - rTp }; excluded i lose STRICTLY
// for every to-tag, so first-max over candidates == full jnp.argmax.
// ---------------------------------------------------------------------------
__global__ __launch_bounds__(32) void viterbi_kernel(
    const float* __restrict__ pots,   // [B, T, K]
    const float* __restrict__ trans,  // [K, K]
    float* __restrict__ out)          // [B, T] float32
{
    extern __shared__ float2 trans2[];            // [64][32]: (T[i][l], T[i][l+32])
    __shared__ unsigned short bp16[(Tn - 1) * 32];  // packed (bi0 | bi1<<8)
    __shared__ unsigned char tags[Tn];
    __shared__ float alpha_f[Kn];

    const int b = blockIdx.x;
    const int l = threadIdx.x;  // lane; owns to-tags l and l+32

    // ---- Prologue: stage transitions (float2-packed) + padded range ----
    const float4* tr4 = (const float4*)trans;
    float tmin = FLT_MAX, tmax = -FLT_MAX;
#pragma unroll
    for (int q = 0; q < 32; q++) {
        const int idx = q * 32 + l;
        const float4 v = tr4[idx];
        tmin = fminf(tmin, fminf(fminf(v.x, v.y), fminf(v.z, v.w)));
        tmax = fmaxf(tmax, fmaxf(fmaxf(v.x, v.y), fmaxf(v.z, v.w)));
        const int base = idx * 4;
        const int i = base >> 6;
        const int c = base & 63;
        if (c < 32) {
            trans2[i * 32 + c + 0].x = v.x;
            trans2[i * 32 + c + 1].x = v.y;
            trans2[i * 32 + c + 2].x = v.z;
            trans2[i * 32 + c + 3].x = v.w;
        } else {
            const int cc = c - 32;
            trans2[i * 32 + cc + 0].y = v.x;
            trans2[i * 32 + cc + 1].y = v.y;
            trans2[i * 32 + cc + 2].y = v.z;
            trans2[i * 32 + cc + 3].y = v.w;
        }
    }
    const unsigned rmn = __reduce_min_sync(0xffffffffu, fmap(tmin));
    const unsigned rmx = __reduce_max_sync(0xffffffffu, fmap(tmax));
    const float r = funmap(rmx) - funmap(rmn);
    const float rTp = r + fabsf(r) * 1e-5f + 0.01f;  // pad only ADDS candidates
    __syncwarp();

    const float* pb = pots + (size_t)b * Tn * Kn;
    int sl = g_seq[b];
    if (sl > Tn) sl = Tn;

    float a_lo = pb[l];
    float a_hi = pb[32 + l];

    if (sl >= Tn) {
        // ---------------- FAST PATH: every step active ----------------------
        unsigned m_lo, m_hi;
        {
            const unsigned am = fmap(a_lo), ah = fmap(a_hi);
            const unsigned wm = __reduce_max_sync(0xffffffffu, am > ah ? am : ah);
            const float thr = funmap(wm) - rTp;
            m_lo = __ballot_sync(0xffffffffu, a_lo >= thr);
            m_hi = __ballot_sync(0xffffffffu, a_hi >= thr);
        }
        float plo[PD], phi[PD];
#pragma unroll
        for (int d = 1; d <= PD; d++) {
            plo[d & (PD - 1)] = pb[d * Kn + l];
            phi[d & (PD - 1)] = pb[d * Kn + 32 + l];
        }
        int t = 1;
#pragma unroll 1
        for (int tb = 0; tb < 63; tb++) {
            STEP_F(t + 0, 1); STEP_F(t + 1, 2); STEP_F(t + 2, 3); STEP_F(t + 3, 4);
            STEP_F(t + 4, 5); STEP_F(t + 5, 6); STEP_F(t + 6, 7); STEP_F(t + 7, 0);
            t += 8;
        }
        STEP_F(t + 0, 1); STEP_F(t + 1, 2); STEP_F(t + 2, 3); STEP_F(t + 3, 4);
        STEP_F(t + 4, 5); STEP_F(t + 5, 6); STEP_F(t + 6, 7);
    } else {
        // ---------------- GENERAL PATH (rare): exact full scan ---------------
#pragma unroll 1
        for (int t = 1; t < Tn; t++) {
            if (t < sl) {
                float best0, best1; int bi0, bi1;
                full_scan64(a_lo, a_hi, trans2, l, best0, best1, bi0, bi1);
                a_lo = pb[t * Kn + l] + best0;
                a_hi = pb[t * Kn + 32 + l] + best1;
                bp16[(t - 1) * 32 + l] =
                    (unsigned short)((unsigned)bi0 | ((unsigned)bi1 << 8));
            } else {
                bp16[(t - 1) * 32 + l] =
                    (unsigned short)((unsigned)l | ((unsigned)(32 + l) << 8));
            }
        }
    }

    // Final alpha -> smem for the backtrace scan
    alpha_f[l] = a_lo;
    alpha_f[32 + l] = a_hi;
    __syncwarp();

    // Backtrace (smem pointer-chase) by lane 0. First max wins.
    if (l == 0) {
        float bv = alpha_f[0];
        int bt = 0;
#pragma unroll 1
        for (int i = 1; i < Kn; i++) {
            const float v = alpha_f[i];
            if (v > bv) { bv = v; bt = i; }
        }
        int tg = bt;
        tags[Tn - 1] = (unsigned char)tg;
#pragma unroll 1
        for (int tt = Tn - 2; tt >= 0; tt--) {
            const unsigned v = bp16[tt * 32 + (tg & 31)];
            tg = (int)((v >> ((tg >> 5) * 8)) & 0xffu);
            tags[tt] = (unsigned char)tg;
        }
    }
    __syncwarp();

    // Coalesced float32 output write (16 per lane).
    float* ob = out + (size_t)b * Tn;
#pragma unroll
    for (int tt = l; tt < Tn; tt += 32) ob[tt] = (float)tags[tt];
}

// ---------------------------------------------------------------------------
extern "C" void kernel_launch(void* const* d_in, const int* in_sizes, int n_in,
                              void* d_out, int out_size) {
    const float* inputs = nullptr;
    const float* transitions = nullptr;
    for (int i = 0; i < n_in; i++) {
        if (in_sizes[i] == Kn * Kn) transitions = (const float*)d_in[i];
        else if (in_sizes[i] == Bn * Tn * Kn) inputs = (const float*)d_in[i];
    }
    if (!inputs) inputs = (const float*)d_in[0];
    if (!transitions) transitions = (const float*)d_in[1];

    float* out = (float*)d_out;

    // Static (~33.5 KB) + 16 KB dynamic -> opt in (host config, capture-safe).
    cudaFuncSetAttribute(viterbi_kernel,
                         cudaFuncAttributeMaxDynamicSharedMemorySize,
                         Kn * 32 * (int)sizeof(float2));

    seqlen_kernel<<<Bn, 256>>>(inputs);
    viterbi_kernel<<<Bn, 32, Kn * 32 * sizeof(float2)>>>(inputs, transitions, out);
}